// round 1
// baseline (speedup 1.0000x reference)
#include <cuda_runtime.h>
#include <cuda_bf16.h>

#define B_ 128
#define T_ 512
#define D_ 256
#define E_ 512
#define H_ 512

// ---------------- scratch (static device globals; no allocation) ----------------
__device__ float g_wcomb[4 * H_ * D_];            // [2048][256], row = gate*512 + h  (gate order i,f,g,o)
__device__ float g_bcomb[4 * H_];                 // [2048]
__device__ float g_xs[134217728];                 // [t][gate][b][h] = 512*4*128*512 (512 MB)
__device__ float g_hbuf[2][B_ * H_];              // double-buffered hidden state
__device__ unsigned int g_cnt;                    // grid barrier counter

__global__ void reset_kernel() { g_cnt = 0u; }

// ---------------- Wcomb = Wgate(2048x512) @ We(512x256) ----------------
__global__ void wcomb_kernel(const float* __restrict__ Wi, const float* __restrict__ Wf,
                             const float* __restrict__ Wg, const float* __restrict__ Wo,
                             const float* __restrict__ We) {
    __shared__ float As[16][65];   // [k][m]
    __shared__ float Bs[16][65];   // [k][n]
    const int bm = blockIdx.y * 64;   // over 2048 rows
    const int bn = blockIdx.x * 64;   // over 256 cols
    const int tid = threadIdx.x;
    float acc[4][4] = {};
    const int tx = tid % 16, ty = tid / 16;

    for (int k0 = 0; k0 < 512; k0 += 16) {
        for (int i = tid; i < 64 * 16; i += 256) {
            int r = i / 16, kk = i % 16;
            int row = bm + r;
            int gate = row >> 9, h = row & 511;
            const float* W = (gate == 0) ? Wi : (gate == 1) ? Wf : (gate == 2) ? Wg : Wo;
            As[kk][r] = W[h * 512 + k0 + kk];
        }
        for (int i = tid; i < 64 * 16; i += 256) {
            int kk = i / 64, c = i % 64;
            Bs[kk][c] = We[(k0 + kk) * 256 + bn + c];
        }
        __syncthreads();
#pragma unroll
        for (int kk = 0; kk < 16; kk++) {
            float a[4], b[4];
#pragma unroll
            for (int i = 0; i < 4; i++) a[i] = As[kk][ty * 4 + i];
#pragma unroll
            for (int j = 0; j < 4; j++) b[j] = Bs[kk][tx * 4 + j];
#pragma unroll
            for (int i = 0; i < 4; i++)
#pragma unroll
                for (int j = 0; j < 4; j++) acc[i][j] += a[i] * b[j];
        }
        __syncthreads();
    }
#pragma unroll
    for (int i = 0; i < 4; i++)
#pragma unroll
        for (int j = 0; j < 4; j++)
            g_wcomb[(bm + ty * 4 + i) * 256 + bn + tx * 4 + j] = acc[i][j];
}

// ---------------- bcomb = Wgate @ be + bgate ----------------
__global__ void bcomb_kernel(const float* __restrict__ Wi, const float* __restrict__ Wf,
                             const float* __restrict__ Wg, const float* __restrict__ Wo,
                             const float* __restrict__ be,
                             const float* __restrict__ bi, const float* __restrict__ bf,
                             const float* __restrict__ bg, const float* __restrict__ bo) {
    int r = blockIdx.x * 256 + threadIdx.x;   // 2048 total
    if (r >= 2048) return;
    int gate = r >> 9, h = r & 511;
    const float* W = (gate == 0) ? Wi : (gate == 1) ? Wf : (gate == 2) ? Wg : Wo;
    const float* bb = (gate == 0) ? bi : (gate == 1) ? bf : (gate == 2) ? bg : bo;
    float s = 0.f;
    for (int e = 0; e < 512; e++) s += W[h * 512 + e] * be[e];
    g_bcomb[r] = s + bb[h];
}

// ---------------- xs = x(65536x256) @ Wcomb^T(256x2048) + bcomb, scattered to [t][g][b][h] ----------------
__global__ void xs_gemm_kernel(const float* __restrict__ x) {
    __shared__ __align__(16) float As[16][132];   // [k][m]
    __shared__ __align__(16) float Bs[16][132];   // [k][n]
    const int bm = blockIdx.x * 128;   // M = 65536, grid.x = 512
    const int bn = blockIdx.y * 128;   // N = 2048,  grid.y = 16
    const int tid = threadIdx.x;
    const int tx = tid % 16, ty = tid / 16;
    float acc[8][8] = {};

    for (int k0 = 0; k0 < 256; k0 += 16) {
        for (int i = tid; i < 512; i += 256) {
            int r = i >> 2, f = i & 3;
            float4 v = *(const float4*)&x[(size_t)(bm + r) * 256 + k0 + f * 4];
            As[f * 4 + 0][r] = v.x; As[f * 4 + 1][r] = v.y;
            As[f * 4 + 2][r] = v.z; As[f * 4 + 3][r] = v.w;
        }
        for (int i = tid; i < 512; i += 256) {
            int c = i >> 2, f = i & 3;
            float4 v = *(const float4*)&g_wcomb[(size_t)(bn + c) * 256 + k0 + f * 4];
            Bs[f * 4 + 0][c] = v.x; Bs[f * 4 + 1][c] = v.y;
            Bs[f * 4 + 2][c] = v.z; Bs[f * 4 + 3][c] = v.w;
        }
        __syncthreads();
#pragma unroll
        for (int kk = 0; kk < 16; kk++) {
            float a[8], b[8];
            *(float4*)&a[0] = *(const float4*)&As[kk][ty * 8];
            *(float4*)&a[4] = *(const float4*)&As[kk][ty * 8 + 4];
            *(float4*)&b[0] = *(const float4*)&Bs[kk][tx * 8];
            *(float4*)&b[4] = *(const float4*)&Bs[kk][tx * 8 + 4];
#pragma unroll
            for (int i = 0; i < 8; i++)
#pragma unroll
                for (int j = 0; j < 8; j++) acc[i][j] += a[i] * b[j];
        }
        __syncthreads();
    }

    float bias[8];
#pragma unroll
    for (int j = 0; j < 8; j++) bias[j] = g_bcomb[bn + tx * 8 + j];

#pragma unroll
    for (int i = 0; i < 8; i++) {
        int m = bm + ty * 8 + i;
        int t = m & 511, bidx = m >> 9;
#pragma unroll
        for (int jj = 0; jj < 2; jj++) {
            int n = bn + tx * 8 + jj * 4;
            int gate = n >> 9, h = n & 511;
            float4 v;
            v.x = acc[i][jj * 4 + 0] + bias[jj * 4 + 0];
            v.y = acc[i][jj * 4 + 1] + bias[jj * 4 + 1];
            v.z = acc[i][jj * 4 + 2] + bias[jj * 4 + 2];
            v.w = acc[i][jj * 4 + 3] + bias[jj * 4 + 3];
            *(float4*)&g_xs[(size_t)((t * 4 + gate) * 128 + bidx) * 512 + h] = v;
        }
    }
}

// ---------------- persistent recurrent scan ----------------
// 128 blocks x 256 threads. Block = (b_chunk in [0,4), h_chunk in [0,32)):
//   32 batches x 16 h-cols x 4 gates = 2048 dot products of length 512 per step.
__global__ void __launch_bounds__(256, 1) scan_kernel(
        const float* __restrict__ h0, const float* __restrict__ c0,
        const float* __restrict__ Ri, const float* __restrict__ Rf,
        const float* __restrict__ Rg, const float* __restrict__ Ro,
        float* __restrict__ out) {
    __shared__ float hs[32][65];      // [b_local][k]
    __shared__ float rs[64][65];      // [col][k], col = gate*16 + h_local
    __shared__ float acc_s[64][33];   // [col][b_local]

    const int tid = threadIdx.x;
    const int bchunk = blockIdx.x >> 5;      // 0..3
    const int hchunk = blockIdx.x & 31;      // 0..31
    const int b0 = bchunk * 32;
    const int hb = hchunk * 16;
    const int bg = tid >> 4;                 // 0..15 -> rows 2bg,2bg+1
    const int cg = tid & 15;                 // 0..15 -> cols 4cg..4cg+3

    // c state in registers: 2 (b,h) pairs per thread
    float creg[2], hlast[2];
#pragma unroll
    for (int q = 0; q < 2; q++) {
        int p = tid * 2 + q;
        int bl = p >> 4, hl = p & 15;
        creg[q] = c0[(b0 + bl) * 512 + hb + hl];
        hlast[q] = 0.f;
    }

    for (int t = 0; t < 512; t++) {
        const float* hprev = (t == 0) ? h0 : g_hbuf[t & 1];
        float acc[2][4] = {};

        for (int k0 = 0; k0 < 512; k0 += 64) {
            // load h tile (cross-SM data -> L2 loads)
#pragma unroll
            for (int ii = 0; ii < 2; ii++) {
                int i = tid + ii * 256;
                int r = i >> 4, f = i & 15;
                float4 v = __ldcg((const float4*)&hprev[(b0 + r) * 512 + k0 + f * 4]);
                hs[r][f * 4 + 0] = v.x; hs[r][f * 4 + 1] = v.y;
                hs[r][f * 4 + 2] = v.z; hs[r][f * 4 + 3] = v.w;
            }
            // load R tile (constant across steps -> L1 resident)
#pragma unroll
            for (int ii = 0; ii < 4; ii++) {
                int i = tid + ii * 256;
                int c = i >> 4, f = i & 15;
                int gate = c >> 4;
                const float* R = (gate == 0) ? Ri : (gate == 1) ? Rf : (gate == 2) ? Rg : Ro;
                float4 v = *(const float4*)&R[(hb + (c & 15)) * 512 + k0 + f * 4];
                rs[c][f * 4 + 0] = v.x; rs[c][f * 4 + 1] = v.y;
                rs[c][f * 4 + 2] = v.z; rs[c][f * 4 + 3] = v.w;
            }
            __syncthreads();
#pragma unroll 16
            for (int kk = 0; kk < 64; kk++) {
                float a0 = hs[2 * bg + 0][kk];
                float a1 = hs[2 * bg + 1][kk];
                float r0 = rs[4 * cg + 0][kk];
                float r1 = rs[4 * cg + 1][kk];
                float r2 = rs[4 * cg + 2][kk];
                float r3 = rs[4 * cg + 3][kk];
                acc[0][0] += a0 * r0; acc[0][1] += a0 * r1;
                acc[0][2] += a0 * r2; acc[0][3] += a0 * r3;
                acc[1][0] += a1 * r0; acc[1][1] += a1 * r1;
                acc[1][2] += a1 * r2; acc[1][3] += a1 * r3;
            }
            __syncthreads();
        }

#pragma unroll
        for (int i = 0; i < 2; i++)
#pragma unroll
            for (int j = 0; j < 4; j++)
                acc_s[4 * cg + j][2 * bg + i] = acc[i][j];
        __syncthreads();

        // pointwise: gates + state update
        const float* xsbase = &g_xs[(size_t)t * 4 * B_ * H_];
        float* hnext = g_hbuf[(t + 1) & 1];
#pragma unroll
        for (int q = 0; q < 2; q++) {
            int p = tid * 2 + q;
            int bl = p >> 4, hl = p & 15;
            int bgl = b0 + bl, hgl = hb + hl;
            float ipre = acc_s[0 + hl][bl]  + xsbase[(size_t)(0 * 128 + bgl) * 512 + hgl];
            float fpre = acc_s[16 + hl][bl] + xsbase[(size_t)(1 * 128 + bgl) * 512 + hgl];
            float gpre = acc_s[32 + hl][bl] + xsbase[(size_t)(2 * 128 + bgl) * 512 + hgl];
            float opre = acc_s[48 + hl][bl] + xsbase[(size_t)(3 * 128 + bgl) * 512 + hgl];
            float ig = 1.f / (1.f + expf(-ipre));
            float fg = 1.f / (1.f + expf(-fpre));
            float gv = tanhf(gpre);
            float og = 1.f / (1.f + expf(-opre));
            float cn = gv * ig + fg * creg[q];
            creg[q] = cn;
            float hn = og * tanhf(cn);
            hlast[q] = hn;
            hnext[bgl * 512 + hgl] = hn;
            out[((size_t)bgl * 512 + t) * 512 + hgl] = hn;
        }

        // grid barrier
        __threadfence();
        __syncthreads();
        if (tid == 0) {
            atomicAdd(&g_cnt, 1u);
            unsigned target = (unsigned)(t + 1) * 128u;
            while (*(volatile unsigned int*)&g_cnt < target) { __nanosleep(64); }
        }
        __syncthreads();
    }

    // epilogue: h_last at 33554432, c_last at 33620 -- 33554432 + 65536
#pragma unroll
    for (int q = 0; q < 2; q++) {
        int p = tid * 2 + q;
        int bl = p >> 4, hl = p & 15;
        size_t idx = (size_t)(b0 + bl) * 512 + hb + hl;
        out[(size_t)33554432 + idx] = hlast[q];
        out[(size_t)33620224 - 256 + idx] = creg[q];   // 33554432 + 65536 = 33619968
    }
}

extern "C" void kernel_launch(void* const* d_in, const int* in_sizes, int n_in,
                              void* d_out, int out_size) {
    const float* x  = (const float*)d_in[0];
    const float* h0 = (const float*)d_in[1];
    const float* c0 = (const float*)d_in[2];
    const float* We = (const float*)d_in[3];
    const float* be = (const float*)d_in[4];
    const float* Wf = (const float*)d_in[5];
    const float* bf = (const float*)d_in[6];
    const float* Wi = (const float*)d_in[7];
    const float* bi = (const float*)d_in[8];
    const float* Wg = (const float*)d_in[9];
    const float* bg = (const float*)d_in[10];
    const float* Wo = (const float*)d_in[11];
    const float* bo = (const float*)d_in[12];
    const float* Rf = (const float*)d_in[13];
    const float* Ri = (const float*)d_in[14];
    const float* Rg = (const float*)d_in[15];
    const float* Ro = (const float*)d_in[16];
    float* out = (float*)d_out;

    reset_kernel<<<1, 1>>>();
    wcomb_kernel<<<dim3(4, 32), 256>>>(Wi, Wf, Wg, Wo, We);
    bcomb_kernel<<<8, 256>>>(Wi, Wf, Wg, Wo, be, bi, bf, bg, bo);
    xs_gemm_kernel<<<dim3(512, 16), 256>>>(x);
    scan_kernel<<<128, 256>>>(h0, c0, Ri, Rf, Rg, Ro, out);
}